// round 1
// baseline (speedup 1.0000x reference)
#include <cuda_runtime.h>
#include <math.h>

#define HW    512
#define CCH   32
#define NCH   8
#define NJOBS 30
#define PATCH 64

// src patch (si*8+sj) for each compact active-k index
__constant__ int c_src[NJOBS] = {
    0*8+0, 1*8+0, 2*8+0, 3*8+0, 4*8+0, 5*8+0, 6*8+0, 7*8+0,
    2*8+2, 4*8+1, 5*8+1, 6*8+1, 4*8+2, 7*8+1, 5*8+2, 4*8+3,
    6*8+2, 7*8+2, 4*8+4, 6*8+3, 5*8+4, 7*8+3, 6*8+4, 5*8+5,
    7*8+4, 6*8+5, 7*8+5, 6*8+6, 7*8+6, 7*8+7
};

// k (0..63) -> compact job index, -1 if inactive
__constant__ int c_kidx[64] = {
     0,  1,  2,  3,  4,  5,  6,  7,   // k=0..7
     8,  9, -1, 10, -1, 11, 12, 13,   // k=8..15
    -1, 14, -1, 15, 16, -1, -1, 17,   // k=16..23
    18, -1, -1, 19, -1, 20, -1, 21,   // k=24..31
    -1, -1, 22, 23, -1, -1, -1, 24,   // k=32..39
    -1, 25, -1, -1, -1, -1, -1, 26,   // k=40..47
    27, -1, -1, -1, -1, -1, -1, 28,   // k=48..55
    -1, -1, -1, -1, -1, -1, -1, 29    // k=56..63
};

// scratch (device globals; no runtime allocation allowed)
__device__ float g_fg  [8 * CCH * 64];                 // pooled sums [b][c][k]
__device__ float g_gate[8 * 64 * CCH];                 // gates [b][k][c]
__device__ float g_B   [8 * NJOBS * NCH * PATCH*PATCH];// conv+relu output per job
__device__ float g_fs5 [8 * NJOBS * CCH * NCH];        // fs5 [job][o(32)][n(8)]

// ---------------------------------------------------------------------------
// Kernel 1: 64x64 block sums of x -> g_fg  (fg mean applied later)
// grid = 8*32*8 = 2048 (b,c,i), block = 256
// ---------------------------------------------------------------------------
__global__ void k_pool(const float* __restrict__ x) {
    int bid = blockIdx.x;
    int i = bid & 7;
    int c = (bid >> 3) & 31;
    int b = bid >> 8;
    const float4* base = (const float4*)(x + ((size_t)(b*CCH + c)*HW + (size_t)i*PATCH)*HW);
    int tid = threadIdx.x;

    float s[8];
#pragma unroll
    for (int j = 0; j < 8; j++) s[j] = 0.f;

#pragma unroll
    for (int j = 0; j < 8; j++) {
#pragma unroll
        for (int it = 0; it < 4; it++) {
            int f  = tid + it * 256;       // 0..1023
            int r  = f >> 4;               // row 0..63
            int c4 = f & 15;               // float4 within 64-col block
            float4 v = __ldg(&base[r*128 + j*16 + c4]);
            s[j] += (v.x + v.y) + (v.z + v.w);
        }
    }

    __shared__ float red[8][8];
    int lane = tid & 31, w = tid >> 5;
#pragma unroll
    for (int j = 0; j < 8; j++) {
#pragma unroll
        for (int off = 16; off; off >>= 1)
            s[j] += __shfl_xor_sync(0xffffffffu, s[j], off);
    }
    if (lane == 0) {
#pragma unroll
        for (int j = 0; j < 8; j++) red[w][j] = s[j];
    }
    __syncthreads();
    if (tid < 8) {
        float t = 0.f;
#pragma unroll
        for (int w2 = 0; w2 < 8; w2++) t += red[w2][tid];
        g_fg[(b*CCH + c)*64 + i*8 + tid] = t;
    }
}

// ---------------------------------------------------------------------------
// Kernel 2: gate MLP  (grid=8 batches, block=32 channels)
// ---------------------------------------------------------------------------
__global__ void k_gate(const float* __restrict__ w12a, const float* __restrict__ b12a,
                       const float* __restrict__ w12b, const float* __restrict__ b12b,
                       const float* __restrict__ w12c, const float* __restrict__ b12c) {
    int b = blockIdx.x;
    int c = threadIdx.x;   // 0..31

    float fg[64];
#pragma unroll
    for (int k = 0; k < 64; k++)
        fg[k] = g_fg[(b*CCH + c)*64 + k] * (1.f / 4096.f);

    float t1[8];
#pragma unroll
    for (int o = 0; o < 8; o++) {
        float s = __ldg(&b12a[o]);
#pragma unroll
        for (int k = 0; k < 64; k++) s = fmaf(__ldg(&w12a[o*64 + k]), fg[k], s);
        t1[o] = fmaxf(s, 0.f);
    }
    float t2[8];
#pragma unroll
    for (int o = 0; o < 8; o++) {
        float s = __ldg(&b12b[o]);
#pragma unroll
        for (int k = 0; k < 8; k++) s = fmaf(__ldg(&w12b[o*8 + k]), t1[k], s);
        t2[o] = fmaxf(s, 0.f);
    }
#pragma unroll
    for (int o = 0; o < 64; o++) {
        float s = __ldg(&b12c[o]);
#pragma unroll
        for (int k = 0; k < 8; k++) s = fmaf(__ldg(&w12c[o*8 + k]), t2[k], s);
        g_gate[(b*64 + o)*CCH + c] = 1.f / (1.f + expf(-s));
    }
}

// ---------------------------------------------------------------------------
// Kernel 3: per-job conv3x3(32->8)+relu -> g_B, then fs2 -> fs3 -> fs5 -> g_fs5
// grid = 240 (b*30+kidx), block = 512.  Each thread owns an 8-pixel row run,
// keeps the 8x8 B accumulators in registers across both passes.
// ---------------------------------------------------------------------------
__global__ void __launch_bounds__(512, 1)
k_conv(const float* __restrict__ x,
       const float* __restrict__ w30, const float* __restrict__ b30,
       const float* __restrict__ w10, const float* __restrict__ b10,
       const float* __restrict__ w11, const float* __restrict__ b11) {
    int job  = blockIdx.x;
    int b    = job / NJOBS;
    int kidx = job % NJOBS;
    int sc = c_src[kidx];
    int si = sc >> 3, sj = sc & 7;
    const float* xp = x + ((size_t)b*CCH*HW + (size_t)si*PATCH)*HW + (size_t)sj*PATCH;

    __shared__ float in_s[66*66];          // 4356  (zero border = SAME padding)
    __shared__ float w_s[CCH*NCH*9];       // 2304  reorganized [c][n][9]
    __shared__ float part[CCH*16*8];       // 4096  fs2 partials [c][warp][n]

    int tid = threadIdx.x;
    for (int t = tid; t < 66*66; t += 512) in_s[t] = 0.f;
    for (int t = tid; t < 2304; t += 512) {
        int n  = t / 288;
        int r  = t % 288;
        int cc = r / 9;
        int ki = r % 9;
        w_s[(cc*NCH + n)*9 + ki] = __ldg(&w30[t]);
    }
    __syncthreads();

    int row = tid >> 3;            // 0..63
    int xb  = (tid & 7) << 3;      // 0,8,...,56

    float acc[8][8];
#pragma unroll
    for (int n = 0; n < 8; n++)
#pragma unroll
        for (int p = 0; p < 8; p++) acc[n][p] = 0.f;

    for (int c = 0; c < CCH; c++) {
        const float* src = xp + (size_t)c*HW*HW;
        for (int t = tid; t < 1024; t += 512) {
            int r = t >> 4, q = t & 15;
            float4 v = __ldg((const float4*)(src + (size_t)r*HW) + q);
            float* d = &in_s[(r+1)*66 + 1 + q*4];
            d[0] = v.x; d[1] = v.y; d[2] = v.z; d[3] = v.w;
        }
        __syncthreads();

#pragma unroll
        for (int dy = 0; dy < 3; dy++) {
            float rr[10];
            const float* rp = &in_s[(row+dy)*66 + xb];
#pragma unroll
            for (int q = 0; q < 10; q++) rr[q] = rp[q];
            const float* wp = &w_s[c*NCH*9 + dy*3];
#pragma unroll
            for (int n = 0; n < 8; n++) {
                float w0 = wp[n*9 + 0];
                float w1 = wp[n*9 + 1];
                float w2 = wp[n*9 + 2];
#pragma unroll
                for (int p = 0; p < 8; p++)
                    acc[n][p] = fmaf(w0, rr[p], fmaf(w1, rr[p+1], fmaf(w2, rr[p+2], acc[n][p])));
            }
        }
        __syncthreads();
    }

    // bias + relu, store B (keep in registers for pass 2)
    size_t Bbase = (size_t)job * NCH * 4096;
#pragma unroll
    for (int n = 0; n < 8; n++) {
        float bb = __ldg(&b30[n]);
#pragma unroll
        for (int p = 0; p < 8; p++) acc[n][p] = fmaxf(acc[n][p] + bb, 0.f);
        float4* d = (float4*)&g_B[Bbase + (size_t)n*4096 + row*64 + xb];
        d[0] = make_float4(acc[n][0], acc[n][1], acc[n][2], acc[n][3]);
        d[1] = make_float4(acc[n][4], acc[n][5], acc[n][6], acc[n][7]);
    }

    // pass 2: fs2[n][c] = sum_l B[n,l] * fs[c,l]
    int lane = tid & 31, wrp = tid >> 5;
    for (int c = 0; c < CCH; c++) {
        const float4* src = (const float4*)(xp + (size_t)c*HW*HW + (size_t)row*HW + xb);
        float4 f0 = __ldg(src);
        float4 f1 = __ldg(src + 1);
        float fv[8] = {f0.x, f0.y, f0.z, f0.w, f1.x, f1.y, f1.z, f1.w};
        float pn[8];
#pragma unroll
        for (int n = 0; n < 8; n++) {
            float s = 0.f;
#pragma unroll
            for (int p = 0; p < 8; p++) s = fmaf(acc[n][p], fv[p], s);
            pn[n] = s;
        }
#pragma unroll
        for (int n = 0; n < 8; n++) {
#pragma unroll
            for (int off = 16; off; off >>= 1)
                pn[n] += __shfl_xor_sync(0xffffffffu, pn[n], off);
        }
        if (lane == 0) {
#pragma unroll
            for (int n = 0; n < 8; n++) part[(c*16 + wrp)*8 + n] = pn[n];
        }
    }
    __syncthreads();

    float* fs2_s = in_s;          // [n*32+c]
    float* fs3_s = in_s + 256;    // [o*32+c]
    if (tid < 256) {
        int cc = tid >> 3, n = tid & 7;
        float s = 0.f;
#pragma unroll
        for (int w2 = 0; w2 < 16; w2++) s += part[(cc*16 + w2)*8 + n];
        fs2_s[n*32 + cc] = s;
    }
    __syncthreads();
    if (tid < 256) {
        int o = tid >> 5, cc = tid & 31;
        float s = __ldg(&b11[o]);
#pragma unroll
        for (int n = 0; n < 8; n++) s = fmaf(__ldg(&w11[o*8 + n]), fs2_s[n*32 + cc], s);
        fs3_s[o*32 + cc] = fmaxf(s, 0.f);
    }
    __syncthreads();
    if (tid < 256) {
        int o = tid >> 3, n = tid & 7;   // fs5[o in 32][n in 8]
        float s = __ldg(&b10[o]);
#pragma unroll
        for (int cc = 0; cc < 32; cc++) s = fmaf(__ldg(&w10[o*32 + cc]), fs3_s[n*32 + cc], s);
        g_fs5[(size_t)job*256 + tid] = fmaxf(s, 0.f);
    }
}

// ---------------------------------------------------------------------------
// Kernel 4: per output patch: M' = (w31 .* g) @ fs5 * bnA, then
//           y = relu(M' @ Bv + cst) + x.   grid = 8*64, block = 256
// ---------------------------------------------------------------------------
__global__ void __launch_bounds__(256)
k_final(const float* __restrict__ x,
        const float* __restrict__ w31, const float* __restrict__ b31,
        const float* __restrict__ gam, const float* __restrict__ bet,
        const float* __restrict__ mea, const float* __restrict__ var,
        float* __restrict__ out) {
    int bid = blockIdx.x;
    int pj = bid & 7, pi = (bid >> 3) & 7, b = bid >> 6;
    int k = (pi + 1) * (pj + 1) - 1;
    int kidx = c_kidx[k];
    int job = b * NJOBS + kidx;

    __shared__ float M_s[256];
    __shared__ float cst_s[32];
    __shared__ float g_s[32];
    __shared__ float A_s[32];
    __shared__ float fs5_s[256];
    __shared__ float B_s[8 * 512];

    int tid = threadIdx.x;
    if (tid < 32) {
        g_s[tid] = g_gate[(b*64 + k)*32 + tid];
        float A  = __ldg(&gam[tid]) * rsqrtf(__ldg(&var[tid]) + 1e-5f);
        A_s[tid] = A;
        cst_s[tid] = (__ldg(&b31[tid]) - __ldg(&mea[tid])) * A + __ldg(&bet[tid]);
    }
    fs5_s[tid] = g_fs5[(size_t)job*256 + tid];
    __syncthreads();
    {
        int o = tid >> 3, n = tid & 7;
        float s = 0.f;
#pragma unroll
        for (int c = 0; c < 32; c++)
            s = fmaf(__ldg(&w31[o*32 + c]) * g_s[c], fs5_s[c*8 + n], s);
        M_s[tid] = s * A_s[o];
    }
    __syncthreads();

    size_t Bbase = (size_t)job * 8 * 4096;
    int lane = tid & 31, w = tid >> 5;

    for (int ch = 0; ch < 8; ch++) {
        __syncthreads();
        for (int t = tid; t < 1024; t += 256) {
            int n = t >> 7, q = t & 127;
            ((float4*)B_s)[n*128 + q] =
                __ldg((const float4*)&g_B[Bbase + (size_t)n*4096 + ch*512] + q);
        }
        __syncthreads();
#pragma unroll
        for (int cc = 0; cc < 4; cc++) {
            int o = w + cc * 8;
            float m[8];
#pragma unroll
            for (int n = 0; n < 8; n++) m[n] = M_s[o*8 + n];
            float cst = cst_s[o];
            size_t base = (((size_t)(b*32 + o)*HW) + (size_t)(pi*64 + ch*8))*HW + pj*64;
#pragma unroll
            for (int it = 0; it < 16; it++) {
                int p = lane + it*32;
                float y = cst;
#pragma unroll
                for (int n = 0; n < 8; n++) y = fmaf(m[n], B_s[n*512 + p], y);
                size_t idx = base + (size_t)(p >> 6)*HW + (p & 63);
                out[idx] = fmaxf(y, 0.f) + __ldg(&x[idx]);
            }
        }
    }
}

// ---------------------------------------------------------------------------
extern "C" void kernel_launch(void* const* d_in, const int* in_sizes, int n_in,
                              void* d_out, int out_size) {
    const float* x     = (const float*)d_in[0];
    const float* w30   = (const float*)d_in[1];
    const float* b30   = (const float*)d_in[2];
    const float* w10   = (const float*)d_in[3];
    const float* b10   = (const float*)d_in[4];
    const float* w11   = (const float*)d_in[5];
    const float* b11   = (const float*)d_in[6];
    const float* w12a  = (const float*)d_in[7];
    const float* b12a  = (const float*)d_in[8];
    const float* w12b  = (const float*)d_in[9];
    const float* b12b  = (const float*)d_in[10];
    const float* w12c  = (const float*)d_in[11];
    const float* b12c  = (const float*)d_in[12];
    const float* w31   = (const float*)d_in[13];
    const float* b31   = (const float*)d_in[14];
    const float* gam   = (const float*)d_in[15];
    const float* bet   = (const float*)d_in[16];
    const float* mea   = (const float*)d_in[17];
    const float* var   = (const float*)d_in[18];
    float* out = (float*)d_out;

    k_pool <<<2048, 256>>>(x);
    k_gate <<<8, 32>>>(w12a, b12a, w12b, b12b, w12c, b12c);
    k_conv <<<240, 512>>>(x, w30, b30, w10, b10, w11, b11);
    k_final<<<512, 256>>>(x, w31, b31, gam, bet, mea, var, out);
}

// round 2
// speedup vs baseline: 1.0410x; 1.0410x over previous
#include <cuda_runtime.h>
#include <math.h>

#define HW    512
#define CCH   32
#define NCH   8
#define NJOBS 30
#define PATCH 64

typedef unsigned long long ull;

// src patch (si*8+sj) for each compact active-k index
__constant__ int c_src[NJOBS] = {
    0*8+0, 1*8+0, 2*8+0, 3*8+0, 4*8+0, 5*8+0, 6*8+0, 7*8+0,
    2*8+2, 4*8+1, 5*8+1, 6*8+1, 4*8+2, 7*8+1, 5*8+2, 4*8+3,
    6*8+2, 7*8+2, 4*8+4, 6*8+3, 5*8+4, 7*8+3, 6*8+4, 5*8+5,
    7*8+4, 6*8+5, 7*8+5, 6*8+6, 7*8+6, 7*8+7
};

// k (0..63) -> compact job index, -1 if inactive
__constant__ int c_kidx[64] = {
     0,  1,  2,  3,  4,  5,  6,  7,
     8,  9, -1, 10, -1, 11, 12, 13,
    -1, 14, -1, 15, 16, -1, -1, 17,
    18, -1, -1, 19, -1, 20, -1, 21,
    -1, -1, 22, 23, -1, -1, -1, 24,
    -1, 25, -1, -1, -1, -1, -1, 26,
    27, -1, -1, -1, -1, -1, -1, 28,
    -1, -1, -1, -1, -1, -1, -1, 29
};

// scratch (device globals; no runtime allocation allowed)
__device__ float g_fg  [8 * CCH * 64];
__device__ float g_gate[8 * 64 * CCH];
__device__ float g_B   [8 * NJOBS * NCH * PATCH*PATCH];
__device__ float g_fs5 [8 * NJOBS * CCH * NCH];
__device__ float g_M   [8 * 64 * CCH * NCH];          // M'[b][pi*8+pj][o][n]

// ---- packed f32x2 helpers (sm_10x) --------------------------------------
__device__ __forceinline__ ull pk2(float lo, float hi) {
    ull r;
    asm("mov.b64 %0, {%1,%2};" : "=l"(r)
        : "r"(__float_as_uint(lo)), "r"(__float_as_uint(hi)));
    return r;
}
__device__ __forceinline__ float2 upk2(ull v) {
    unsigned int a, b;
    asm("mov.b64 {%0,%1}, %2;" : "=r"(a), "=r"(b) : "l"(v));
    return make_float2(__uint_as_float(a), __uint_as_float(b));
}
__device__ __forceinline__ void fma2(ull &d, ull a, ull b) {
    asm("fma.rn.f32x2 %0, %1, %2, %0;" : "+l"(d) : "l"(a), "l"(b));
}

// ---------------------------------------------------------------------------
// Kernel 1: 64x64 block sums of x -> g_fg
// ---------------------------------------------------------------------------
__global__ void k_pool(const float* __restrict__ x) {
    int bid = blockIdx.x;
    int i = bid & 7;
    int c = (bid >> 3) & 31;
    int b = bid >> 8;
    const float4* base = (const float4*)(x + ((size_t)(b*CCH + c)*HW + (size_t)i*PATCH)*HW);
    int tid = threadIdx.x;

    float s[8];
#pragma unroll
    for (int j = 0; j < 8; j++) s[j] = 0.f;

#pragma unroll
    for (int j = 0; j < 8; j++) {
#pragma unroll
        for (int it = 0; it < 4; it++) {
            int f  = tid + it * 256;
            int r  = f >> 4;
            int c4 = f & 15;
            float4 v = __ldg(&base[r*128 + j*16 + c4]);
            s[j] += (v.x + v.y) + (v.z + v.w);
        }
    }

    __shared__ float red[8][8];
    int lane = tid & 31, w = tid >> 5;
#pragma unroll
    for (int j = 0; j < 8; j++) {
#pragma unroll
        for (int off = 16; off; off >>= 1)
            s[j] += __shfl_xor_sync(0xffffffffu, s[j], off);
    }
    if (lane == 0) {
#pragma unroll
        for (int j = 0; j < 8; j++) red[w][j] = s[j];
    }
    __syncthreads();
    if (tid < 8) {
        float t = 0.f;
#pragma unroll
        for (int w2 = 0; w2 < 8; w2++) t += red[w2][tid];
        g_fg[(b*CCH + c)*64 + i*8 + tid] = t;
    }
}

// ---------------------------------------------------------------------------
// Kernel 2: gate MLP
// ---------------------------------------------------------------------------
__global__ void k_gate(const float* __restrict__ w12a, const float* __restrict__ b12a,
                       const float* __restrict__ w12b, const float* __restrict__ b12b,
                       const float* __restrict__ w12c, const float* __restrict__ b12c) {
    int b = blockIdx.x;
    int c = threadIdx.x;

    float fg[64];
#pragma unroll
    for (int k = 0; k < 64; k++)
        fg[k] = g_fg[(b*CCH + c)*64 + k] * (1.f / 4096.f);

    float t1[8];
#pragma unroll
    for (int o = 0; o < 8; o++) {
        float s = __ldg(&b12a[o]);
#pragma unroll
        for (int k = 0; k < 64; k++) s = fmaf(__ldg(&w12a[o*64 + k]), fg[k], s);
        t1[o] = fmaxf(s, 0.f);
    }
    float t2[8];
#pragma unroll
    for (int o = 0; o < 8; o++) {
        float s = __ldg(&b12b[o]);
#pragma unroll
        for (int k = 0; k < 8; k++) s = fmaf(__ldg(&w12b[o*8 + k]), t1[k], s);
        t2[o] = fmaxf(s, 0.f);
    }
#pragma unroll
    for (int o = 0; o < 64; o++) {
        float s = __ldg(&b12c[o]);
#pragma unroll
        for (int k = 0; k < 8; k++) s = fmaf(__ldg(&w12c[o*8 + k]), t2[k], s);
        g_gate[(b*64 + o)*CCH + c] = 1.f / (1.f + expf(-s));
    }
}

// ---------------------------------------------------------------------------
// Kernel 3: per-job conv3x3(32->8)+relu -> g_B (packed f32x2 math),
//           then fs2 -> fs3 -> fs5 -> g_fs5
// grid = 240, block = 512
// ---------------------------------------------------------------------------
__global__ void __launch_bounds__(512, 1)
k_conv(const float* __restrict__ x,
       const float* __restrict__ w30, const float* __restrict__ b30,
       const float* __restrict__ w10, const float* __restrict__ b10,
       const float* __restrict__ w11, const float* __restrict__ b11) {
    int job  = blockIdx.x;
    int b    = job / NJOBS;
    int kidx = job % NJOBS;
    int sc = c_src[kidx];
    int si = sc >> 3, sj = sc & 7;
    const float* xp = x + ((size_t)b*CCH*HW + (size_t)si*PATCH)*HW + (size_t)sj*PATCH;

    __shared__ float in_s[66*66];       // zero border = SAME padding; reused as fs2 partials
    __shared__ ull   w2_s[CCH*NCH*9];   // duplicated-packed weights [c][n][9]
    __shared__ float fs_s[512];         // fs2 (256) + fs3 (256)

    int tid = threadIdx.x;
    for (int t = tid; t < 66*66; t += 512) in_s[t] = 0.f;
    for (int t = tid; t < 2304; t += 512) {
        int n  = t / 288;
        int r  = t % 288;
        int cc = r / 9;
        int ki = r % 9;
        float v = __ldg(&w30[t]);
        w2_s[(cc*NCH + n)*9 + ki] = pk2(v, v);
    }
    __syncthreads();

    int row = tid >> 3;            // 0..63
    int xb  = (tid & 7) << 3;      // 0,8,...,56
    int r0  = tid >> 4;            // tile-fill row (0..31)
    int q0  = tid & 15;            // tile-fill float4 idx

    ull acc2[8][4];
#pragma unroll
    for (int n = 0; n < 8; n++)
#pragma unroll
        for (int q = 0; q < 4; q++) acc2[n][q] = 0ULL;

    // preload channel 0 tile
    float4 v0, v1;
    {
        const float4* s = (const float4*)xp;
        v0 = __ldg(s + r0*128 + q0);
        v1 = __ldg(s + (r0+32)*128 + q0);
    }
    {
        float* d0 = &in_s[(r0+1)*66 + 1 + q0*4];
        d0[0]=v0.x; d0[1]=v0.y; d0[2]=v0.z; d0[3]=v0.w;
        float* d1 = &in_s[(r0+33)*66 + 1 + q0*4];
        d1[0]=v1.x; d1[1]=v1.y; d1[2]=v1.z; d1[3]=v1.w;
    }
    __syncthreads();

    for (int c = 0; c < CCH; c++) {
        float4 n0, n1;
        if (c < CCH-1) {
            const float4* s = (const float4*)(xp + (size_t)(c+1)*HW*HW);
            n0 = __ldg(s + r0*128 + q0);
            n1 = __ldg(s + (r0+32)*128 + q0);
        }

#pragma unroll
        for (int dy = 0; dy < 3; dy++) {
            float rr[10];
            const float* rp = &in_s[(row+dy)*66 + xb];
#pragma unroll
            for (int q = 0; q < 10; q++) rr[q] = rp[q];
            ull E0[5], E1[4];
#pragma unroll
            for (int q = 0; q < 5; q++) E0[q] = pk2(rr[2*q], rr[2*q+1]);
#pragma unroll
            for (int q = 0; q < 4; q++) E1[q] = pk2(rr[2*q+1], rr[2*q+2]);
            const ull* wp = &w2_s[(c*NCH)*9 + dy*3];
#pragma unroll
            for (int n = 0; n < 8; n++) {
                ull W0 = wp[n*9 + 0];
                ull W1 = wp[n*9 + 1];
                ull W2 = wp[n*9 + 2];
#pragma unroll
                for (int q = 0; q < 4; q++) {
                    fma2(acc2[n][q], W0, E0[q]);
                    fma2(acc2[n][q], W1, E1[q]);
                    fma2(acc2[n][q], W2, E0[q+1]);
                }
            }
        }
        __syncthreads();
        if (c < CCH-1) {
            float* d0 = &in_s[(r0+1)*66 + 1 + q0*4];
            d0[0]=n0.x; d0[1]=n0.y; d0[2]=n0.z; d0[3]=n0.w;
            float* d1 = &in_s[(r0+33)*66 + 1 + q0*4];
            d1[0]=n1.x; d1[1]=n1.y; d1[2]=n1.z; d1[3]=n1.w;
        }
        __syncthreads();
    }

    // bias + relu, store B; keep packed acc for pass 2
    size_t Bbase = (size_t)job * NCH * 4096;
#pragma unroll
    for (int n = 0; n < 8; n++) {
        float bb = __ldg(&b30[n]);
        float r8[8];
#pragma unroll
        for (int q = 0; q < 4; q++) {
            float2 u = upk2(acc2[n][q]);
            r8[2*q]   = fmaxf(u.x + bb, 0.f);
            r8[2*q+1] = fmaxf(u.y + bb, 0.f);
            acc2[n][q] = pk2(r8[2*q], r8[2*q+1]);
        }
        float4* d = (float4*)&g_B[Bbase + (size_t)n*4096 + row*64 + xb];
        d[0] = make_float4(r8[0], r8[1], r8[2], r8[3]);
        d[1] = make_float4(r8[4], r8[5], r8[6], r8[7]);
    }

    // pass 2: fs2[n][c] = sum_l B[n,l] * fs[c,l]  (part overlaid on in_s)
    float* part = in_s;   // [c][warp][n] : 32*16*8 = 4096 floats
    int lane = tid & 31, wrp = tid >> 5;
    for (int c = 0; c < CCH; c++) {
        const float4* src = (const float4*)(xp + (size_t)c*HW*HW + (size_t)row*HW + xb);
        float4 f0 = __ldg(src);
        float4 f1 = __ldg(src + 1);
        ull fv2[4];
        fv2[0] = pk2(f0.x, f0.y); fv2[1] = pk2(f0.z, f0.w);
        fv2[2] = pk2(f1.x, f1.y); fv2[3] = pk2(f1.z, f1.w);
        float pn[8];
#pragma unroll
        for (int n = 0; n < 8; n++) {
            ull s2 = 0ULL;
#pragma unroll
            for (int q = 0; q < 4; q++) fma2(s2, acc2[n][q], fv2[q]);
            float2 u = upk2(s2);
            pn[n] = u.x + u.y;
        }
#pragma unroll
        for (int n = 0; n < 8; n++) {
#pragma unroll
            for (int off = 16; off; off >>= 1)
                pn[n] += __shfl_xor_sync(0xffffffffu, pn[n], off);
        }
        if (lane == 0) {
#pragma unroll
            for (int n = 0; n < 8; n++) part[(c*16 + wrp)*8 + n] = pn[n];
        }
    }
    __syncthreads();

    float* fs2_s = fs_s;
    float* fs3_s = fs_s + 256;
    if (tid < 256) {
        int cc = tid >> 3, n = tid & 7;
        float s = 0.f;
#pragma unroll
        for (int w2 = 0; w2 < 16; w2++) s += part[(cc*16 + w2)*8 + n];
        fs2_s[n*32 + cc] = s;
    }
    __syncthreads();
    if (tid < 256) {
        int o = tid >> 5, cc = tid & 31;
        float s = __ldg(&b11[o]);
#pragma unroll
        for (int n = 0; n < 8; n++) s = fmaf(__ldg(&w11[o*8 + n]), fs2_s[n*32 + cc], s);
        fs3_s[o*32 + cc] = fmaxf(s, 0.f);
    }
    __syncthreads();
    if (tid < 256) {
        int o = tid >> 3, n = tid & 7;
        float s = __ldg(&b10[o]);
#pragma unroll
        for (int cc = 0; cc < 32; cc++) s = fmaf(__ldg(&w10[o*32 + cc]), fs3_s[n*32 + cc], s);
        g_fs5[(size_t)job*256 + tid] = fmaxf(s, 0.f);
    }
}

// ---------------------------------------------------------------------------
// Kernel 3.5: M'[b][pi][pj][o][n] = bnA[o] * sum_c w31[o,c]*g[b,k,c]*fs5[job,c,n]
// grid = 512, block = 256
// ---------------------------------------------------------------------------
__global__ void k_mprep(const float* __restrict__ w31,
                        const float* __restrict__ gam, const float* __restrict__ var) {
    int bid = blockIdx.x;
    int b = bid >> 6;
    int pp = bid & 63;
    int pi = pp >> 3, pj = pp & 7;
    int kk = (pi + 1) * (pj + 1) - 1;
    int job = b * NJOBS + c_kidx[kk];

    __shared__ float gs[32], fs5s[256];
    int tid = threadIdx.x;
    if (tid < 32) gs[tid] = g_gate[(b*64 + kk)*32 + tid];
    fs5s[tid] = g_fs5[(size_t)job*256 + tid];
    __syncthreads();

    int o = tid >> 3, n = tid & 7;
    float s = 0.f;
#pragma unroll
    for (int c = 0; c < 32; c++)
        s = fmaf(__ldg(&w31[o*32 + c]) * gs[c], fs5s[c*8 + n], s);
    float A = __ldg(&gam[o]) * rsqrtf(__ldg(&var[o]) + 1e-5f);
    g_M[bid*256 + tid] = s * A;
}

// ---------------------------------------------------------------------------
// Kernel 4: streaming epilogue. grid = b*pi*row = 4096, block = 512
// (one thread per output column; all 32 channels)
// ---------------------------------------------------------------------------
__global__ void __launch_bounds__(512)
k_final(const float* __restrict__ x,
        const float* __restrict__ b31,
        const float* __restrict__ gam, const float* __restrict__ bet,
        const float* __restrict__ mea, const float* __restrict__ var,
        float* __restrict__ out) {
    int bid = blockIdx.x;
    int r  = bid & 63;
    int pi = (bid >> 6) & 7;
    int b  = bid >> 9;

    __shared__ float M_s[2048];    // 8 pj * 32 o * 8 n
    __shared__ float cst_s[32];

    int tid = threadIdx.x;
    for (int t = tid; t < 2048; t += 512)
        M_s[t] = g_M[((size_t)(b*64 + pi*8 + (t >> 8)))*256 + (t & 255)];
    if (tid < 32) {
        float A = __ldg(&gam[tid]) * rsqrtf(__ldg(&var[tid]) + 1e-5f);
        cst_s[tid] = (__ldg(&b31[tid]) - __ldg(&mea[tid])) * A + __ldg(&bet[tid]);
    }

    int pj  = tid >> 6;
    int col = tid & 63;
    int kk  = (pi + 1) * (pj + 1) - 1;
    int job = b * NJOBS + c_kidx[kk];

    float Bv[8];
    size_t Bbase = (size_t)job * NCH * 4096 + (size_t)r*64 + col;
#pragma unroll
    for (int n = 0; n < 8; n++) Bv[n] = __ldg(&g_B[Bbase + (size_t)n*4096]);
    __syncthreads();

    const float* Mp = &M_s[pj*256];
    size_t base0 = ((size_t)b*32*HW + (size_t)(pi*64 + r))*HW + tid;

#pragma unroll 4
    for (int o = 0; o < 32; o++) {
        float y = cst_s[o];
#pragma unroll
        for (int n = 0; n < 8; n++) y = fmaf(Mp[o*8 + n], Bv[n], y);
        size_t idx = base0 + (size_t)o*HW*HW;
        out[idx] = fmaxf(y, 0.f) + __ldg(&x[idx]);
    }
}

// ---------------------------------------------------------------------------
extern "C" void kernel_launch(void* const* d_in, const int* in_sizes, int n_in,
                              void* d_out, int out_size) {
    const float* x     = (const float*)d_in[0];
    const float* w30   = (const float*)d_in[1];
    const float* b30   = (const float*)d_in[2];
    const float* w10   = (const float*)d_in[3];
    const float* b10   = (const float*)d_in[4];
    const float* w11   = (const float*)d_in[5];
    const float* b11   = (const float*)d_in[6];
    const float* w12a  = (const float*)d_in[7];
    const float* b12a  = (const float*)d_in[8];
    const float* w12b  = (const float*)d_in[9];
    const float* b12b  = (const float*)d_in[10];
    const float* w12c  = (const float*)d_in[11];
    const float* b12c  = (const float*)d_in[12];
    const float* w31   = (const float*)d_in[13];
    const float* b31   = (const float*)d_in[14];
    const float* gam   = (const float*)d_in[15];
    const float* bet   = (const float*)d_in[16];
    const float* mea   = (const float*)d_in[17];
    const float* var   = (const float*)d_in[18];
    float* out = (float*)d_out;

    k_pool <<<2048, 256>>>(x);
    k_gate <<<8, 32>>>(w12a, b12a, w12b, b12b, w12c, b12c);
    k_conv <<<240, 512>>>(x, w30, b30, w10, b10, w11, b11);
    k_mprep<<<512, 256>>>(w31, gam, var);
    k_final<<<4096, 512>>>(x, b31, gam, bet, mea, var, out);
}

// round 3
// speedup vs baseline: 1.0512x; 1.0098x over previous
#include <cuda_runtime.h>
#include <math.h>

#define HW    512
#define CCH   32
#define NCH   8
#define NJOBS 30
#define PATCH 64

typedef unsigned long long ull;

// src patch (si*8+sj) for each compact active-k index
__constant__ int c_src[NJOBS] = {
    0*8+0, 1*8+0, 2*8+0, 3*8+0, 4*8+0, 5*8+0, 6*8+0, 7*8+0,
    2*8+2, 4*8+1, 5*8+1, 6*8+1, 4*8+2, 7*8+1, 5*8+2, 4*8+3,
    6*8+2, 7*8+2, 4*8+4, 6*8+3, 5*8+4, 7*8+3, 6*8+4, 5*8+5,
    7*8+4, 6*8+5, 7*8+5, 6*8+6, 7*8+6, 7*8+7
};

// k (0..63) -> compact job index, -1 if inactive
__constant__ int c_kidx[64] = {
     0,  1,  2,  3,  4,  5,  6,  7,
     8,  9, -1, 10, -1, 11, 12, 13,
    -1, 14, -1, 15, 16, -1, -1, 17,
    18, -1, -1, 19, -1, 20, -1, 21,
    -1, -1, 22, 23, -1, -1, -1, 24,
    -1, 25, -1, -1, -1, -1, -1, 26,
    27, -1, -1, -1, -1, -1, -1, 28,
    -1, -1, -1, -1, -1, -1, -1, 29
};

// scratch (device globals)
__device__ float g_fg  [8 * CCH * 64];
__device__ float g_gate[8 * 64 * CCH];
__device__ float g_B   [8 * NJOBS * NCH * PATCH*PATCH];
__device__ float g_fs2 [8 * NJOBS * NCH * CCH];      // [job][n][c], atomically accumulated
__device__ float g_fs5 [8 * NJOBS * CCH * NCH];
__device__ float g_M   [8 * 64 * CCH * NCH];         // M'[b][pi*8+pj][o][n]

// ---- packed f32x2 helpers (sm_10x) --------------------------------------
__device__ __forceinline__ ull pk2(float lo, float hi) {
    ull r;
    asm("mov.b64 %0, {%1,%2};" : "=l"(r)
        : "r"(__float_as_uint(lo)), "r"(__float_as_uint(hi)));
    return r;
}
__device__ __forceinline__ float2 upk2(ull v) {
    unsigned int a, b;
    asm("mov.b64 {%0,%1}, %2;" : "=r"(a), "=r"(b) : "l"(v));
    return make_float2(__uint_as_float(a), __uint_as_float(b));
}
__device__ __forceinline__ void fma2(ull &d, ull a, ull b) {
    asm("fma.rn.f32x2 %0, %1, %2, %0;" : "+l"(d) : "l"(a), "l"(b));
}

// ---------------------------------------------------------------------------
// Kernel 1: 64x64 block sums of x -> g_fg ; also zeroes g_fs2
// grid = 2048 (b,c,i), block = 256
// ---------------------------------------------------------------------------
__global__ void k_pool(const float* __restrict__ x) {
    int bid = blockIdx.x;
    // zero g_fs2 (61440 floats) using first 60 blocks
    if (bid < 60) {
        int base = bid * 1024;
#pragma unroll
        for (int it = 0; it < 4; it++)
            g_fs2[base + threadIdx.x + it*256] = 0.f;
    }

    int i = bid & 7;
    int c = (bid >> 3) & 31;
    int b = bid >> 8;
    const float4* base = (const float4*)(x + ((size_t)(b*CCH + c)*HW + (size_t)i*PATCH)*HW);
    int tid = threadIdx.x;

    float s[8];
#pragma unroll
    for (int j = 0; j < 8; j++) s[j] = 0.f;

#pragma unroll
    for (int j = 0; j < 8; j++) {
#pragma unroll
        for (int it = 0; it < 4; it++) {
            int f  = tid + it * 256;
            int r  = f >> 4;
            int c4 = f & 15;
            float4 v = __ldg(&base[r*128 + j*16 + c4]);
            s[j] += (v.x + v.y) + (v.z + v.w);
        }
    }

    __shared__ float red[8][8];
    int lane = tid & 31, w = tid >> 5;
#pragma unroll
    for (int j = 0; j < 8; j++) {
#pragma unroll
        for (int off = 16; off; off >>= 1)
            s[j] += __shfl_xor_sync(0xffffffffu, s[j], off);
    }
    if (lane == 0) {
#pragma unroll
        for (int j = 0; j < 8; j++) red[w][j] = s[j];
    }
    __syncthreads();
    if (tid < 8) {
        float t = 0.f;
#pragma unroll
        for (int w2 = 0; w2 < 8; w2++) t += red[w2][tid];
        g_fg[(b*CCH + c)*64 + i*8 + tid] = t;
    }
}

// ---------------------------------------------------------------------------
// Kernel 2: gate MLP
// ---------------------------------------------------------------------------
__global__ void k_gate(const float* __restrict__ w12a, const float* __restrict__ b12a,
                       const float* __restrict__ w12b, const float* __restrict__ b12b,
                       const float* __restrict__ w12c, const float* __restrict__ b12c) {
    int b = blockIdx.x;
    int c = threadIdx.x;

    float fg[64];
#pragma unroll
    for (int k = 0; k < 64; k++)
        fg[k] = g_fg[(b*CCH + c)*64 + k] * (1.f / 4096.f);

    float t1[8];
#pragma unroll
    for (int o = 0; o < 8; o++) {
        float s = __ldg(&b12a[o]);
#pragma unroll
        for (int k = 0; k < 64; k++) s = fmaf(__ldg(&w12a[o*64 + k]), fg[k], s);
        t1[o] = fmaxf(s, 0.f);
    }
    float t2[8];
#pragma unroll
    for (int o = 0; o < 8; o++) {
        float s = __ldg(&b12b[o]);
#pragma unroll
        for (int k = 0; k < 8; k++) s = fmaf(__ldg(&w12b[o*8 + k]), t1[k], s);
        t2[o] = fmaxf(s, 0.f);
    }
#pragma unroll
    for (int o = 0; o < 64; o++) {
        float s = __ldg(&b12c[o]);
#pragma unroll
        for (int k = 0; k < 8; k++) s = fmaf(__ldg(&w12c[o*8 + k]), t2[k], s);
        g_gate[(b*64 + o)*CCH + c] = 1.f / (1.f + expf(-s));
    }
}

// ---------------------------------------------------------------------------
// Kernel 3: conv3x3(32->8)+relu -> g_B, fs2 partials -> g_fs2 (atomic)
// grid = 960 (job*4 + rowquad), block = 256. Each CTA: 16 output rows.
// Each thread: 4-px run for 8 output channels (packed f32x2 accumulators).
// ---------------------------------------------------------------------------
__global__ void __launch_bounds__(256, 2)
k_conv(const float* __restrict__ x,
       const float* __restrict__ w30, const float* __restrict__ b30) {
    int bid   = blockIdx.x;
    int job   = bid >> 2;
    int quad  = bid & 3;
    int rbase = quad * 16;
    int b     = job / NJOBS;
    int kidx  = job % NJOBS;
    int sc = c_src[kidx];
    int si = sc >> 3, sj = sc & 7;
    const float* xp = x + ((size_t)b*CCH*HW + (size_t)si*PATCH)*HW + (size_t)sj*PATCH;

    __shared__ float in_s[18*66];        // 18 rows (1 halo each side), zero borders
    __shared__ ull   w2_s[CCH*NCH*9];    // duplicated-packed weights [c][n][9]
    __shared__ float part[CCH*8*8];      // fs2 partials [c][warp][n]

    int tid = threadIdx.x;
    for (int t = tid; t < 18*66; t += 256) in_s[t] = 0.f;
    for (int t = tid; t < 2304; t += 256) {
        int n  = t / 288;
        int r  = t % 288;
        int cc = r / 9;
        int ki = r % 9;
        float v = __ldg(&w30[t]);
        w2_s[(cc*NCH + n)*9 + ki] = pk2(v, v);
    }

    // fixed fill slots for this thread (288 float4 slots per channel tile)
    int fr0 = tid >> 4, fq0 = tid & 15;          // slot tid
    int gr0 = rbase - 1 + fr0;
    bool h0 = (gr0 >= 0 && gr0 < 64);
    int fr1 = (tid + 256) >> 4, fq1 = tid & 15;  // slot tid+256 (tid<32 only)
    int gr1 = rbase - 1 + fr1;
    bool h1 = (tid < 32) && (gr1 >= 0 && gr1 < 64);

    int rl  = tid >> 4;           // output row 0..15 (local)
    int xb  = (tid & 15) << 2;    // col base 0,4,...,60

    ull acc2[8][2];
#pragma unroll
    for (int n = 0; n < 8; n++) { acc2[n][0] = 0ULL; acc2[n][1] = 0ULL; }

    // prefetch channel 0
    float4 p0, p1;
    if (h0) p0 = __ldg((const float4*)(xp + (size_t)gr0*HW) + fq0);
    if (h1) p1 = __ldg((const float4*)(xp + (size_t)gr1*HW) + fq1);
    __syncthreads();
    if (h0) { float* d = &in_s[fr0*66 + 1 + fq0*4]; d[0]=p0.x; d[1]=p0.y; d[2]=p0.z; d[3]=p0.w; }
    if (h1) { float* d = &in_s[fr1*66 + 1 + fq1*4]; d[0]=p1.x; d[1]=p1.y; d[2]=p1.z; d[3]=p1.w; }
    __syncthreads();

    for (int c = 0; c < CCH; c++) {
        if (c < CCH-1) {
            const float* src = xp + (size_t)(c+1)*HW*HW;
            if (h0) p0 = __ldg((const float4*)(src + (size_t)gr0*HW) + fq0);
            if (h1) p1 = __ldg((const float4*)(src + (size_t)gr1*HW) + fq1);
        }

#pragma unroll
        for (int dy = 0; dy < 3; dy++) {
            float rr[6];
            const float* rp = &in_s[(rl+dy)*66 + xb];
#pragma unroll
            for (int q = 0; q < 6; q++) rr[q] = rp[q];
            ull E0[3], E1[2];
            E0[0] = pk2(rr[0], rr[1]); E0[1] = pk2(rr[2], rr[3]); E0[2] = pk2(rr[4], rr[5]);
            E1[0] = pk2(rr[1], rr[2]); E1[1] = pk2(rr[3], rr[4]);
            const ull* wp = &w2_s[(c*NCH)*9 + dy*3];
#pragma unroll
            for (int n = 0; n < 8; n++) {
                ull W0 = wp[n*9 + 0];
                ull W1 = wp[n*9 + 1];
                ull W2 = wp[n*9 + 2];
                fma2(acc2[n][0], W0, E0[0]);
                fma2(acc2[n][0], W1, E1[0]);
                fma2(acc2[n][0], W2, E0[1]);
                fma2(acc2[n][1], W0, E0[1]);
                fma2(acc2[n][1], W1, E1[1]);
                fma2(acc2[n][1], W2, E0[2]);
            }
        }
        __syncthreads();
        if (c < CCH-1) {
            if (h0) { float* d = &in_s[fr0*66 + 1 + fq0*4]; d[0]=p0.x; d[1]=p0.y; d[2]=p0.z; d[3]=p0.w; }
            if (h1) { float* d = &in_s[fr1*66 + 1 + fq1*4]; d[0]=p1.x; d[1]=p1.y; d[2]=p1.z; d[3]=p1.w; }
        }
        __syncthreads();
    }

    // bias + relu, store B (keep packed acc for pass 2)
    int grow = rbase + rl;
    size_t Bbase = (size_t)job * NCH * 4096;
#pragma unroll
    for (int n = 0; n < 8; n++) {
        float bb = __ldg(&b30[n]);
        float2 u0 = upk2(acc2[n][0]);
        float2 u1 = upk2(acc2[n][1]);
        float r0 = fmaxf(u0.x + bb, 0.f);
        float r1 = fmaxf(u0.y + bb, 0.f);
        float r2 = fmaxf(u1.x + bb, 0.f);
        float r3 = fmaxf(u1.y + bb, 0.f);
        acc2[n][0] = pk2(r0, r1);
        acc2[n][1] = pk2(r2, r3);
        *(float4*)&g_B[Bbase + (size_t)n*4096 + grow*64 + xb] = make_float4(r0, r1, r2, r3);
    }

    // pass 2: fs2[n][c] partial = sum over this CTA's 16 rows
    int lane = tid & 31, wrp = tid >> 5;
    for (int c = 0; c < CCH; c++) {
        float4 f = __ldg((const float4*)(xp + (size_t)c*HW*HW + (size_t)grow*HW + xb));
        ull fv0 = pk2(f.x, f.y), fv1 = pk2(f.z, f.w);
        float pn[8];
#pragma unroll
        for (int n = 0; n < 8; n++) {
            ull s2 = 0ULL;
            fma2(s2, acc2[n][0], fv0);
            fma2(s2, acc2[n][1], fv1);
            float2 u = upk2(s2);
            pn[n] = u.x + u.y;
        }
#pragma unroll
        for (int n = 0; n < 8; n++) {
#pragma unroll
            for (int off = 16; off; off >>= 1)
                pn[n] += __shfl_xor_sync(0xffffffffu, pn[n], off);
        }
        if (lane == 0) {
#pragma unroll
            for (int n = 0; n < 8; n++) part[(c*8 + wrp)*8 + n] = pn[n];
        }
    }
    __syncthreads();

    // reduce 8 warps, atomic into g_fs2[job][n][c]
    {
        int cc = tid >> 3, n = tid & 7;
        float s = 0.f;
#pragma unroll
        for (int w2 = 0; w2 < 8; w2++) s += part[(cc*8 + w2)*8 + n];
        atomicAdd(&g_fs2[(size_t)job*256 + n*32 + cc], s);
    }
}

// ---------------------------------------------------------------------------
// Kernel 3.25: fs2 -> fs3 -> fs5. grid = 240, block = 256
// ---------------------------------------------------------------------------
__global__ void k_fs5(const float* __restrict__ w10, const float* __restrict__ b10,
                      const float* __restrict__ w11, const float* __restrict__ b11) {
    int job = blockIdx.x;
    __shared__ float fs2_s[256], fs3_s[256];
    int tid = threadIdx.x;
    fs2_s[tid] = g_fs2[(size_t)job*256 + tid];   // [n*32+c]
    __syncthreads();
    {
        int o = tid >> 5, cc = tid & 31;
        float s = __ldg(&b11[o]);
#pragma unroll
        for (int n = 0; n < 8; n++) s = fmaf(__ldg(&w11[o*8 + n]), fs2_s[n*32 + cc], s);
        fs3_s[o*32 + cc] = fmaxf(s, 0.f);
    }
    __syncthreads();
    {
        int o = tid >> 3, n = tid & 7;
        float s = __ldg(&b10[o]);
#pragma unroll
        for (int cc = 0; cc < 32; cc++) s = fmaf(__ldg(&w10[o*32 + cc]), fs3_s[n*32 + cc], s);
        g_fs5[(size_t)job*256 + tid] = fmaxf(s, 0.f);
    }
}

// ---------------------------------------------------------------------------
// Kernel 3.5: M'[b][pi][pj][o][n]
// ---------------------------------------------------------------------------
__global__ void k_mprep(const float* __restrict__ w31,
                        const float* __restrict__ gam, const float* __restrict__ var) {
    int bid = blockIdx.x;
    int b = bid >> 6;
    int pp = bid & 63;
    int pi = pp >> 3, pj = pp & 7;
    int kk = (pi + 1) * (pj + 1) - 1;
    int job = b * NJOBS + c_kidx[kk];

    __shared__ float gs[32], fs5s[256];
    int tid = threadIdx.x;
    if (tid < 32) gs[tid] = g_gate[(b*64 + kk)*32 + tid];
    fs5s[tid] = g_fs5[(size_t)job*256 + tid];
    __syncthreads();

    int o = tid >> 3, n = tid & 7;
    float s = 0.f;
#pragma unroll
    for (int c = 0; c < 32; c++)
        s = fmaf(__ldg(&w31[o*32 + c]) * gs[c], fs5s[c*8 + n], s);
    float A = __ldg(&gam[o]) * rsqrtf(__ldg(&var[o]) + 1e-5f);
    g_M[bid*256 + tid] = s * A;
}

// ---------------------------------------------------------------------------
// Kernel 4: streaming epilogue. grid = 2048 (b,pi,rowgroup), block = 256.
// Each thread: one float4 of columns, all 32 output channels.
// ---------------------------------------------------------------------------
__global__ void __launch_bounds__(256, 3)
k_final(const float* __restrict__ x,
        const float* __restrict__ b31,
        const float* __restrict__ gam, const float* __restrict__ bet,
        const float* __restrict__ mea, const float* __restrict__ var,
        float* __restrict__ out) {
    int bid = blockIdx.x;
    int rg = bid & 31;
    int pi = (bid >> 5) & 7;
    int b  = bid >> 8;

    __shared__ float M_s[2048];    // [pj][o][n]
    __shared__ float cst_s[32];

    int tid = threadIdx.x;
#pragma unroll
    for (int it = 0; it < 8; it++) {
        int t = tid + it*256;
        M_s[t] = g_M[((size_t)(b*64 + pi*8 + (t >> 8)))*256 + (t & 255)];
    }
    if (tid < 32) {
        float A = __ldg(&gam[tid]) * rsqrtf(__ldg(&var[tid]) + 1e-5f);
        cst_s[tid] = (__ldg(&b31[tid]) - __ldg(&mea[tid])) * A + __ldg(&bet[tid]);
    }

    int row = rg*2 + (tid >> 7);         // patch row 0..63
    int rem = tid & 127;
    int pj  = rem >> 4;
    int c4  = (rem & 15) << 2;
    int kk  = (pi + 1) * (pj + 1) - 1;
    int job = b * NJOBS + c_kidx[kk];

    // B values: 8 channels x 4 cols, packed
    ull bp[8][2];
    size_t Bbase = (size_t)job * NCH * 4096 + (size_t)row*64 + c4;
#pragma unroll
    for (int n = 0; n < 8; n++) {
        float4 v = __ldg((const float4*)&g_B[Bbase + (size_t)n*4096]);
        bp[n][0] = pk2(v.x, v.y);
        bp[n][1] = pk2(v.z, v.w);
    }
    __syncthreads();

    const float* Mp = &M_s[pj*256];
    size_t base0 = ((size_t)(b*32)*HW + (size_t)(pi*64 + row))*HW + (size_t)(pj*64 + c4);

#pragma unroll 4
    for (int o = 0; o < 32; o++) {
        size_t idx = base0 + (size_t)o*HW*HW;
        float4 xv = __ldcs((const float4*)&x[idx]);
        float cst = cst_s[o];
        ull y0 = pk2(cst, cst);
        ull y1 = y0;
#pragma unroll
        for (int n = 0; n < 8; n++) {
            float m = Mp[o*8 + n];
            ull mm = pk2(m, m);
            fma2(y0, mm, bp[n][0]);
            fma2(y1, mm, bp[n][1]);
        }
        float2 u0 = upk2(y0), u1 = upk2(y1);
        float4 r;
        r.x = fmaxf(u0.x, 0.f) + xv.x;
        r.y = fmaxf(u0.y, 0.f) + xv.y;
        r.z = fmaxf(u1.x, 0.f) + xv.z;
        r.w = fmaxf(u1.y, 0.f) + xv.w;
        __stcs((float4*)&out[idx], r);
    }
}

// ---------------------------------------------------------------------------
extern "C" void kernel_launch(void* const* d_in, const int* in_sizes, int n_in,
                              void* d_out, int out_size) {
    const float* x     = (const float*)d_in[0];
    const float* w30   = (const float*)d_in[1];
    const float* b30   = (const float*)d_in[2];
    const float* w10   = (const float*)d_in[3];
    const float* b10   = (const float*)d_in[4];
    const float* w11   = (const float*)d_in[5];
    const float* b11   = (const float*)d_in[6];
    const float* w12a  = (const float*)d_in[7];
    const float* b12a  = (const float*)d_in[8];
    const float* w12b  = (const float*)d_in[9];
    const float* b12b  = (const float*)d_in[10];
    const float* w12c  = (const float*)d_in[11];
    const float* b12c  = (const float*)d_in[12];
    const float* w31   = (const float*)d_in[13];
    const float* b31   = (const float*)d_in[14];
    const float* gam   = (const float*)d_in[15];
    const float* bet   = (const float*)d_in[16];
    const float* mea   = (const float*)d_in[17];
    const float* var   = (const float*)d_in[18];
    float* out = (float*)d_out;

    k_pool <<<2048, 256>>>(x);
    k_gate <<<8, 32>>>(w12a, b12a, w12b, b12b, w12c, b12c);
    k_conv <<<960, 256>>>(x, w30, b30);
    k_fs5  <<<240, 256>>>(w10, b10, w11, b11);
    k_mprep<<<512, 256>>>(w31, gam, var);
    k_final<<<2048, 256>>>(x, b31, gam, bet, mea, var, out);
}